// round 7
// baseline (speedup 1.0000x reference)
#include <cuda_runtime.h>
#include <cstdint>

#define NN      50000
#define EE      800000
#define ET      (EE + NN)
#define IN_DIM  256
#define HID     32
#define HEADS   4
#define OUT_DIM 40
#define F1      128
#define F2      160
#define SLOPE   0.2f
#define FULLMASK 0xffffffffu

// ---------------- scratch ----------------
__device__ float g_xc1[(size_t)NN * 256];   // [xl1 | xr1]
__device__ float g_xc2[(size_t)NN * 320];   // [xl2 | xr2]
__device__ float g_h  [(size_t)NN * F1];
__device__ int   g_deg[NN];
__device__ int   g_rowptr[NN + 1];
__device__ int   g_cursor[NN];
__device__ int   g_csrsrc[ET];

// ---------------- CSR build ----------------
__global__ void count_kernel(const int* __restrict__ edst)
{
    int idx = blockIdx.x * blockDim.x + threadIdx.x;
    if (idx >= ET) return;
    int d = (idx < EE) ? edst[idx] : idx - EE;
    atomicAdd(&g_deg[d], 1);
}

__global__ void scan_kernel()
{
    __shared__ int ssum[1024];
    int t = threadIdx.x;
    const int CH = (NN + 1023) / 1024;
    int lo = t * CH;
    int hi = min(lo + CH, NN);
    int s = 0;
    for (int i = lo; i < hi; i++) s += g_deg[i];
    ssum[t] = s;
    __syncthreads();
    for (int off = 1; off < 1024; off <<= 1) {
        int v = (t >= off) ? ssum[t - off] : 0;
        __syncthreads();
        ssum[t] += v;
        __syncthreads();
    }
    int base = (t == 0) ? 0 : ssum[t - 1];
    for (int i = lo; i < hi; i++) {
        g_rowptr[i] = base;
        g_cursor[i] = base;
        base += g_deg[i];
    }
    if (t == 0) g_rowptr[NN] = ET;
}

__global__ void scatter_kernel(const int* __restrict__ esrc, const int* __restrict__ edst)
{
    int idx = blockIdx.x * blockDim.x + threadIdx.x;
    if (idx >= ET) return;
    int s, d;
    if (idx < EE) { s = esrc[idx]; d = edst[idx]; }
    else          { s = d = idx - EE; }
    int pos = atomicAdd(&g_cursor[d], 1);
    g_csrsrc[pos] = s;
}

// ---------------- TF32 GEMM, cp.async double-buffered, fused concat+bias ----------------
__device__ __forceinline__ uint32_t f2tf(float f) {
    uint32_t r;
    asm("cvt.rna.tf32.f32 %0, %1;" : "=r"(r) : "f"(f));
    return r;
}
__device__ __forceinline__ void cpa16(uint32_t d, const void* s, int sz) {
    asm volatile("cp.async.cg.shared.global [%0], [%1], 16, %2;"
                 :: "r"(d), "l"(s), "r"(sz));
}

// C[M, 2*Nh] = A[M,K] @ [Wl | Wr] + [bl | br]
__global__ __launch_bounds__(256, 2) void gemm_tf32_fused(
    const float* __restrict__ A, const float* __restrict__ Wl,
    const float* __restrict__ Wr, const float* __restrict__ bl,
    const float* __restrict__ br, float* __restrict__ C,
    int M, int K, int Nh)
{
    const int N = 2 * Nh;
    __shared__ uint32_t As[2][16][136];
    __shared__ float    Bs[2][16][136];
    int tid = threadIdx.x, lane = tid & 31, warp = tid >> 5;
    int wm = warp & 3, wn = warp >> 2;
    int rowBase = blockIdx.y * 128, colBase = blockIdx.x * 128;
    int grp = lane >> 2, tig = lane & 3;

    float acc[2][8][4];
    #pragma unroll
    for (int mt = 0; mt < 2; mt++)
        #pragma unroll
        for (int nt = 0; nt < 8; nt++)
            #pragma unroll
            for (int c = 0; c < 4; c++) acc[mt][nt][c] = 0.f;

    int nIter = K >> 4;

    float4 pa, pb;
    // prologue: tile 0
    {
        int gr = rowBase + (tid >> 1);
        int kc = (tid & 1) * 8;
        pa = make_float4(0.f, 0.f, 0.f, 0.f); pb = pa;
        if (gr < M) {
            pa = *(const float4*)(A + (size_t)gr * K + kc);
            pb = *(const float4*)(A + (size_t)gr * K + kc + 4);
        }
    }
    {
        int rB = tid >> 4;
        int cB = (tid & 15) * 8;
        #pragma unroll
        for (int i = 0; i < 2; i++) {
            int gc = colBase + cB + i * 4;
            const float* src = Wl; int sz = 0;
            if (gc < Nh)      { src = Wl + (size_t)rB * Nh + gc;        sz = 16; }
            else if (gc < N)  { src = Wr + (size_t)rB * Nh + (gc - Nh); sz = 16; }
            cpa16((uint32_t)__cvta_generic_to_shared(&Bs[0][rB][cB + i * 4]), src, sz);
        }
    }
    {
        int r = tid >> 1, c4 = (tid & 1) * 8;
        As[0][c4 + 0][r] = f2tf(pa.x); As[0][c4 + 1][r] = f2tf(pa.y);
        As[0][c4 + 2][r] = f2tf(pa.z); As[0][c4 + 3][r] = f2tf(pa.w);
        As[0][c4 + 4][r] = f2tf(pb.x); As[0][c4 + 5][r] = f2tf(pb.y);
        As[0][c4 + 6][r] = f2tf(pb.z); As[0][c4 + 7][r] = f2tf(pb.w);
    }
    asm volatile("cp.async.commit_group;");

    int buf = 0;
    for (int it = 0; it < nIter; it++) {
        asm volatile("cp.async.wait_group 0;");
        __syncthreads();
        bool more = (it + 1 < nIter);
        if (more) {
            int k0 = (it + 1) << 4;
            int gr = rowBase + (tid >> 1);
            int kc = k0 + (tid & 1) * 8;
            pa = make_float4(0.f, 0.f, 0.f, 0.f); pb = pa;
            if (gr < M) {
                pa = *(const float4*)(A + (size_t)gr * K + kc);
                pb = *(const float4*)(A + (size_t)gr * K + kc + 4);
            }
            int rB = tid >> 4;
            int cB = (tid & 15) * 8;
            #pragma unroll
            for (int i = 0; i < 2; i++) {
                int gc = colBase + cB + i * 4;
                const float* src = Wl; int sz = 0;
                if (gc < Nh)      { src = Wl + (size_t)(k0 + rB) * Nh + gc;        sz = 16; }
                else if (gc < N)  { src = Wr + (size_t)(k0 + rB) * Nh + (gc - Nh); sz = 16; }
                cpa16((uint32_t)__cvta_generic_to_shared(&Bs[buf ^ 1][rB][cB + i * 4]), src, sz);
            }
            asm volatile("cp.async.commit_group;");
        }

        #pragma unroll
        for (int ks = 0; ks < 16; ks += 8) {
            uint32_t af[2][4], bf[8][2];
            #pragma unroll
            for (int mt = 0; mt < 2; mt++) {
                int m = wm * 32 + mt * 16;
                af[mt][0] = As[buf][ks + tig][m + grp];
                af[mt][1] = As[buf][ks + tig][m + grp + 8];
                af[mt][2] = As[buf][ks + tig + 4][m + grp];
                af[mt][3] = As[buf][ks + tig + 4][m + grp + 8];
            }
            #pragma unroll
            for (int nt = 0; nt < 8; nt++) {
                int nb = wn * 64 + nt * 8;
                bf[nt][0] = f2tf(Bs[buf][ks + tig][nb + grp]);
                bf[nt][1] = f2tf(Bs[buf][ks + tig + 4][nb + grp]);
            }
            #pragma unroll
            for (int mt = 0; mt < 2; mt++)
                #pragma unroll
                for (int nt = 0; nt < 8; nt++) {
                    asm volatile(
                        "mma.sync.aligned.m16n8k8.row.col.f32.tf32.tf32.f32 "
                        "{%0,%1,%2,%3}, {%4,%5,%6,%7}, {%8,%9}, {%0,%1,%2,%3};"
                        : "+f"(acc[mt][nt][0]), "+f"(acc[mt][nt][1]),
                          "+f"(acc[mt][nt][2]), "+f"(acc[mt][nt][3])
                        : "r"(af[mt][0]), "r"(af[mt][1]), "r"(af[mt][2]), "r"(af[mt][3]),
                          "r"(bf[nt][0]), "r"(bf[nt][1]));
                }
        }

        if (more) {
            int r = tid >> 1, c4 = (tid & 1) * 8;
            int b = buf ^ 1;
            As[b][c4 + 0][r] = f2tf(pa.x); As[b][c4 + 1][r] = f2tf(pa.y);
            As[b][c4 + 2][r] = f2tf(pa.z); As[b][c4 + 3][r] = f2tf(pa.w);
            As[b][c4 + 4][r] = f2tf(pb.x); As[b][c4 + 5][r] = f2tf(pb.y);
            As[b][c4 + 6][r] = f2tf(pb.z); As[b][c4 + 7][r] = f2tf(pb.w);
        }
        buf ^= 1;
    }

    // epilogue: fused bias from bl/br
    #pragma unroll
    for (int mt = 0; mt < 2; mt++) {
        #pragma unroll
        for (int nt = 0; nt < 8; nt++) {
            int row0 = rowBase + wm * 32 + mt * 16 + grp;
            int col0 = colBase + wn * 64 + nt * 8 + tig * 2;
            if (col0 < N) {
                float b0 = (col0     < Nh) ? bl[col0]     : br[col0 - Nh];
                float b1 = (col0 + 1 < Nh) ? bl[col0 + 1] : br[col0 + 1 - Nh];
                if (row0 < M) {
                    float2 o = make_float2(acc[mt][nt][0] + b0, acc[mt][nt][1] + b1);
                    *(float2*)(C + (size_t)row0 * N + col0) = o;
                }
                if (row0 + 8 < M) {
                    float2 o = make_float2(acc[mt][nt][2] + b0, acc[mt][nt][3] + b1);
                    *(float2*)(C + (size_t)(row0 + 8) * N + col0) = o;
                }
            }
        }
    }
}

// ---------------- layer 1 agg: warp/node, 4 edges per warp-iteration ----------------
// lane = (eslot<<3) | fs : eslot in 0..3 selects edge, fs in 0..7 selects 16 feats.
// Per-head logit: fs pair (2k, 2k+1) covers head k's 32 feats -> shfl_xor 1.
__global__ __launch_bounds__(256) void agg1_kernel(
    const float* __restrict__ xc, const int* __restrict__ rowptr,
    const int* __restrict__ csrsrc, const float* __restrict__ att,
    const float* __restrict__ bias, float* __restrict__ hout)
{
    int node = (blockIdx.x * blockDim.x + threadIdx.x) >> 5;
    int lane = threadIdx.x & 31;
    if (node >= NN) return;
    int eslot = lane >> 3, fs = lane & 7;

    const float* vp = xc + (size_t)node * 256 + 128 + fs * 16;
    float4 vr0 = *(const float4*)(vp);
    float4 vr1 = *(const float4*)(vp + 4);
    float4 vr2 = *(const float4*)(vp + 8);
    float4 vr3 = *(const float4*)(vp + 12);
    float4 va0 = *(const float4*)(att + fs * 16);
    float4 va1 = *(const float4*)(att + fs * 16 + 4);
    float4 va2 = *(const float4*)(att + fs * 16 + 8);
    float4 va3 = *(const float4*)(att + fs * 16 + 12);

    int beg = rowptr[node], end = rowptr[node + 1];
    int iters = (end - beg + 3) >> 2;
    int sSafe = csrsrc[beg];

    float4 a0 = make_float4(0.f, 0.f, 0.f, 0.f);
    float4 a1 = a0, a2 = a0, a3 = a0;
    float ssum = 0.f;

    int idx = beg + eslot;
    for (int it = 0; it < iters; it++) {
        bool valid = idx < end;
        int s = valid ? csrsrc[idx] : sSafe;
        const float* sp = xc + (size_t)s * 256 + fs * 16;
        float4 c0 = *(const float4*)(sp);
        float4 c1 = *(const float4*)(sp + 4);
        float4 c2 = *(const float4*)(sp + 8);
        float4 c3 = *(const float4*)(sp + 12);

        float g, p = 0.f;
        g = c0.x + vr0.x; g = g > 0.f ? g : SLOPE * g; p += g * va0.x;
        g = c0.y + vr0.y; g = g > 0.f ? g : SLOPE * g; p += g * va0.y;
        g = c0.z + vr0.z; g = g > 0.f ? g : SLOPE * g; p += g * va0.z;
        g = c0.w + vr0.w; g = g > 0.f ? g : SLOPE * g; p += g * va0.w;
        g = c1.x + vr1.x; g = g > 0.f ? g : SLOPE * g; p += g * va1.x;
        g = c1.y + vr1.y; g = g > 0.f ? g : SLOPE * g; p += g * va1.y;
        g = c1.z + vr1.z; g = g > 0.f ? g : SLOPE * g; p += g * va1.z;
        g = c1.w + vr1.w; g = g > 0.f ? g : SLOPE * g; p += g * va1.w;
        g = c2.x + vr2.x; g = g > 0.f ? g : SLOPE * g; p += g * va2.x;
        g = c2.y + vr2.y; g = g > 0.f ? g : SLOPE * g; p += g * va2.y;
        g = c2.z + vr2.z; g = g > 0.f ? g : SLOPE * g; p += g * va2.z;
        g = c2.w + vr2.w; g = g > 0.f ? g : SLOPE * g; p += g * va2.w;
        g = c3.x + vr3.x; g = g > 0.f ? g : SLOPE * g; p += g * va3.x;
        g = c3.y + vr3.y; g = g > 0.f ? g : SLOPE * g; p += g * va3.y;
        g = c3.z + vr3.z; g = g > 0.f ? g : SLOPE * g; p += g * va3.z;
        g = c3.w + vr3.w; g = g > 0.f ? g : SLOPE * g; p += g * va3.w;

        // head logit: fs pairs (0,1),(2,3),(4,5),(6,7) each cover one head's 32 feats
        float sum = p + __shfl_xor_sync(FULLMASK, p, 1);
        float a = valid ? __expf(sum) : 0.f;

        a0.x += a * c0.x; a0.y += a * c0.y; a0.z += a * c0.z; a0.w += a * c0.w;
        a1.x += a * c1.x; a1.y += a * c1.y; a1.z += a * c1.z; a1.w += a * c1.w;
        a2.x += a * c2.x; a2.y += a * c2.y; a2.z += a * c2.z; a2.w += a * c2.w;
        a3.x += a * c3.x; a3.y += a * c3.y; a3.z += a * c3.z; a3.w += a * c3.w;
        ssum += a;
        idx += 4;
    }

    // reduce across 4 edge slots (shfl 8, 16)
    #pragma unroll
    for (int off = 8; off <= 16; off <<= 1) {
        a0.x += __shfl_xor_sync(FULLMASK, a0.x, off);
        a0.y += __shfl_xor_sync(FULLMASK, a0.y, off);
        a0.z += __shfl_xor_sync(FULLMASK, a0.z, off);
        a0.w += __shfl_xor_sync(FULLMASK, a0.w, off);
        a1.x += __shfl_xor_sync(FULLMASK, a1.x, off);
        a1.y += __shfl_xor_sync(FULLMASK, a1.y, off);
        a1.z += __shfl_xor_sync(FULLMASK, a1.z, off);
        a1.w += __shfl_xor_sync(FULLMASK, a1.w, off);
        a2.x += __shfl_xor_sync(FULLMASK, a2.x, off);
        a2.y += __shfl_xor_sync(FULLMASK, a2.y, off);
        a2.z += __shfl_xor_sync(FULLMASK, a2.z, off);
        a2.w += __shfl_xor_sync(FULLMASK, a2.w, off);
        a3.x += __shfl_xor_sync(FULLMASK, a3.x, off);
        a3.y += __shfl_xor_sync(FULLMASK, a3.y, off);
        a3.z += __shfl_xor_sync(FULLMASK, a3.z, off);
        a3.w += __shfl_xor_sync(FULLMASK, a3.w, off);
        ssum += __shfl_xor_sync(FULLMASK, ssum, off);
    }

    if (eslot == 0) {
        float inv = 1.f / (ssum + 1e-16f);
        float4 b0 = *(const float4*)(bias + fs * 16);
        float4 b1 = *(const float4*)(bias + fs * 16 + 4);
        float4 b2 = *(const float4*)(bias + fs * 16 + 8);
        float4 b3 = *(const float4*)(bias + fs * 16 + 12);
        float4 o0, o1, o2, o3;
        o0.x = a0.x * inv + b0.x; o0.y = a0.y * inv + b0.y;
        o0.z = a0.z * inv + b0.z; o0.w = a0.w * inv + b0.w;
        o1.x = a1.x * inv + b1.x; o1.y = a1.y * inv + b1.y;
        o1.z = a1.z * inv + b1.z; o1.w = a1.w * inv + b1.w;
        o2.x = a2.x * inv + b2.x; o2.y = a2.y * inv + b2.y;
        o2.z = a2.z * inv + b2.z; o2.w = a2.w * inv + b2.w;
        o3.x = a3.x * inv + b3.x; o3.y = a3.y * inv + b3.y;
        o3.z = a3.z * inv + b3.z; o3.w = a3.w * inv + b3.w;
        o0.x = o0.x > 0.f ? o0.x : (__expf(o0.x) - 1.f);
        o0.y = o0.y > 0.f ? o0.y : (__expf(o0.y) - 1.f);
        o0.z = o0.z > 0.f ? o0.z : (__expf(o0.z) - 1.f);
        o0.w = o0.w > 0.f ? o0.w : (__expf(o0.w) - 1.f);
        o1.x = o1.x > 0.f ? o1.x : (__expf(o1.x) - 1.f);
        o1.y = o1.y > 0.f ? o1.y : (__expf(o1.y) - 1.f);
        o1.z = o1.z > 0.f ? o1.z : (__expf(o1.z) - 1.f);
        o1.w = o1.w > 0.f ? o1.w : (__expf(o1.w) - 1.f);
        o2.x = o2.x > 0.f ? o2.x : (__expf(o2.x) - 1.f);
        o2.y = o2.y > 0.f ? o2.y : (__expf(o2.y) - 1.f);
        o2.z = o2.z > 0.f ? o2.z : (__expf(o2.z) - 1.f);
        o2.w = o2.w > 0.f ? o2.w : (__expf(o2.w) - 1.f);
        o3.x = o3.x > 0.f ? o3.x : (__expf(o3.x) - 1.f);
        o3.y = o3.y > 0.f ? o3.y : (__expf(o3.y) - 1.f);
        o3.z = o3.z > 0.f ? o3.z : (__expf(o3.z) - 1.f);
        o3.w = o3.w > 0.f ? o3.w : (__expf(o3.w) - 1.f);
        float* op = hout + (size_t)node * F1 + fs * 16;
        *(float4*)(op)      = o0;
        *(float4*)(op + 4)  = o1;
        *(float4*)(op + 8)  = o2;
        *(float4*)(op + 12) = o3;
    }
}

// ---------------- layer 2 agg: warp/node, half-warp/edge, depth-2 prefetch ----------------
__global__ __launch_bounds__(256) void agg2_kernel(
    const float* __restrict__ xc, const int* __restrict__ rowptr,
    const int* __restrict__ csrsrc, const float* __restrict__ att,
    const float* __restrict__ bias, float* __restrict__ out)
{
    int node = (blockIdx.x * blockDim.x + threadIdx.x) >> 5;
    int lane = threadIdx.x & 31;
    if (node >= NN) return;
    int sub = lane >> 4, l = lane & 15;
    int base = l * 10;   // head = l>>2

    float2 vr[5], va[5];
    const float* vp = xc + (size_t)node * 320 + 160 + base;
    #pragma unroll
    for (int j = 0; j < 5; j++) {
        vr[j] = *(const float2*)(vp + 2 * j);
        va[j] = *(const float2*)(att + base + 2 * j);
    }

    int beg = rowptr[node], end = rowptr[node + 1];
    int deg = end - beg;
    int iters = (deg + 1) >> 1;

    float2 acc[5];
    #pragma unroll
    for (int j = 0; j < 5; j++) acc[j] = make_float2(0.f, 0.f);
    float ssum = 0.f;

    int idx = beg + sub;
    bool v = idx < end;
    int s = v ? csrsrc[idx] : csrsrc[beg];
    float2 cur[5];
    {
        const float* sp = xc + (size_t)s * 320 + base;
        #pragma unroll
        for (int j = 0; j < 5; j++) cur[j] = *(const float2*)(sp + 2 * j);
    }

    for (int it = 0; it < iters; it++) {
        int idxn = idx + 2;
        bool vn = idxn < end;
        int sn = vn ? csrsrc[idxn] : csrsrc[beg];
        float2 nxt[5];
        {
            const float* sp = xc + (size_t)sn * 320 + base;
            #pragma unroll
            for (int j = 0; j < 5; j++) nxt[j] = *(const float2*)(sp + 2 * j);
        }
        float sum = 0.f;
        #pragma unroll
        for (int j = 0; j < 5; j++) {
            float g = cur[j].x + vr[j].x; g = g > 0.f ? g : SLOPE * g; sum += g * va[j].x;
            g       = cur[j].y + vr[j].y; g = g > 0.f ? g : SLOPE * g; sum += g * va[j].y;
        }
        sum += __shfl_xor_sync(FULLMASK, sum, 1);
        sum += __shfl_xor_sync(FULLMASK, sum, 2);
        float a = v ? __expf(sum) : 0.f;
        #pragma unroll
        for (int j = 0; j < 5; j++) { acc[j].x += a * cur[j].x; acc[j].y += a * cur[j].y; }
        ssum += a;
        #pragma unroll
        for (int j = 0; j < 5; j++) cur[j] = nxt[j];
        v = vn; idx = idxn;
    }

    #pragma unroll
    for (int j = 0; j < 5; j++) {
        acc[j].x += __shfl_xor_sync(FULLMASK, acc[j].x, 16);
        acc[j].y += __shfl_xor_sync(FULLMASK, acc[j].y, 16);
    }
    ssum += __shfl_xor_sync(FULLMASK, ssum, 16);

    float inv = 1.f / (ssum + 1e-16f);
    #pragma unroll
    for (int j = 0; j < 5; j++) {
        float vx = acc[j].x * inv, vy = acc[j].y * inv;
        vx += __shfl_xor_sync(FULLMASK, vx, 4);
        vx += __shfl_xor_sync(FULLMASK, vx, 8);
        vy += __shfl_xor_sync(FULLMASK, vy, 4);
        vy += __shfl_xor_sync(FULLMASK, vy, 8);
        acc[j].x = vx; acc[j].y = vy;
    }

    if (sub == 0 && l < 4) {
        #pragma unroll
        for (int j = 0; j < 5; j++) {
            float2 o;
            o.x = 0.25f * acc[j].x + bias[base + 2 * j];
            o.y = 0.25f * acc[j].y + bias[base + 2 * j + 1];
            *(float2*)(out + (size_t)node * OUT_DIM + base + 2 * j) = o;
        }
    }
}

// ---------------- host ----------------
struct Ptrs {
    float *xc1, *xc2, *h;
    int *deg, *rowptr, *csrsrc;
};
static Ptrs P;
static cudaStream_t g_s2;
static cudaEvent_t g_ev1, g_ev2;
static bool g_init = false;

extern "C" void kernel_launch(void* const* d_in, const int* in_sizes, int n_in,
                              void* d_out, int out_size)
{
    if (!g_init) {
        cudaGetSymbolAddress((void**)&P.xc1,    g_xc1);
        cudaGetSymbolAddress((void**)&P.xc2,    g_xc2);
        cudaGetSymbolAddress((void**)&P.h,      g_h);
        cudaGetSymbolAddress((void**)&P.deg,    g_deg);
        cudaGetSymbolAddress((void**)&P.rowptr, g_rowptr);
        cudaGetSymbolAddress((void**)&P.csrsrc, g_csrsrc);
        cudaStreamCreateWithFlags(&g_s2, cudaStreamNonBlocking);
        cudaEventCreateWithFlags(&g_ev1, cudaEventDisableTiming);
        cudaEventCreateWithFlags(&g_ev2, cudaEventDisableTiming);
        g_init = true;
    }

    const float* x     = (const float*)d_in[0];
    const int*   ei    = (const int*)  d_in[1];
    const float* Wl1   = (const float*)d_in[2];
    const float* bl1   = (const float*)d_in[3];
    const float* Wr1   = (const float*)d_in[4];
    const float* br1   = (const float*)d_in[5];
    const float* att1  = (const float*)d_in[6];
    const float* bias1 = (const float*)d_in[7];
    const float* Wl2   = (const float*)d_in[8];
    const float* bl2   = (const float*)d_in[9];
    const float* Wr2   = (const float*)d_in[10];
    const float* br2   = (const float*)d_in[11];
    const float* att2  = (const float*)d_in[12];
    const float* bias2 = (const float*)d_in[13];
    float* out = (float*)d_out;

    const int* esrc = ei;
    const int* edst = ei + EE;

    // fork: CSR build on side stream, concurrent with GEMM1
    cudaEventRecord(g_ev1, 0);
    cudaStreamWaitEvent(g_s2, g_ev1, 0);
    cudaMemsetAsync(P.deg, 0, NN * sizeof(int), g_s2);
    count_kernel<<<(ET + 255) / 256, 256, 0, g_s2>>>(edst);
    scan_kernel<<<1, 1024, 0, g_s2>>>();
    scatter_kernel<<<(ET + 255) / 256, 256, 0, g_s2>>>(esrc, edst);
    cudaEventRecord(g_ev2, g_s2);

    // ----- layer 1 GEMM (main stream) -----
    {
        dim3 grid(2, (NN + 127) / 128);
        gemm_tf32_fused<<<grid, 256>>>(x, Wl1, Wr1, bl1, br1, P.xc1, NN, IN_DIM, F1);
    }
    // join: agg1 needs both GEMM1 and CSR
    cudaStreamWaitEvent(0, g_ev2, 0);
    agg1_kernel<<<(NN * 32 + 255) / 256, 256>>>(P.xc1, P.rowptr, P.csrsrc, att1, bias1, P.h);

    // ----- layer 2 -----
    {
        dim3 grid(3, (NN + 127) / 128);
        gemm_tf32_fused<<<grid, 256>>>(P.h, Wl2, Wr2, bl2, br2, P.xc2, NN, F1, F2);
    }
    agg2_kernel<<<(NN * 32 + 255) / 256, 256>>>(P.xc2, P.rowptr, P.csrsrc, att2, bias2, out);
}

// round 8
// speedup vs baseline: 1.0872x; 1.0872x over previous
#include <cuda_runtime.h>
#include <cstdint>

#define NN      50000
#define EE      800000
#define ET      (EE + NN)
#define IN_DIM  256
#define HID     32
#define HEADS   4
#define OUT_DIM 40
#define F1      128
#define F2      160
#define SLOPE   0.2f
#define FULLMASK 0xffffffffu
#define D1 4
#define D2 4

// ---------------- scratch ----------------
__device__ float g_xc1[(size_t)NN * 256];   // [xl1 | xr1]
__device__ float g_xc2[(size_t)NN * 320];   // [xl2 | xr2]
__device__ float g_h  [(size_t)NN * F1];
__device__ int   g_deg[NN];
__device__ int   g_rowptr[NN + 1];
__device__ int   g_cursor[NN];
__device__ int   g_csrsrc[ET];

// ---------------- CSR build ----------------
__global__ void count_kernel(const int* __restrict__ edst)
{
    int idx = blockIdx.x * blockDim.x + threadIdx.x;
    if (idx >= ET) return;
    int d = (idx < EE) ? edst[idx] : idx - EE;
    atomicAdd(&g_deg[d], 1);
}

__global__ void scan_kernel()
{
    __shared__ int ssum[1024];
    int t = threadIdx.x;
    const int CH = (NN + 1023) / 1024;
    int lo = t * CH;
    int hi = min(lo + CH, NN);
    int s = 0;
    for (int i = lo; i < hi; i++) s += g_deg[i];
    ssum[t] = s;
    __syncthreads();
    for (int off = 1; off < 1024; off <<= 1) {
        int v = (t >= off) ? ssum[t - off] : 0;
        __syncthreads();
        ssum[t] += v;
        __syncthreads();
    }
    int base = (t == 0) ? 0 : ssum[t - 1];
    for (int i = lo; i < hi; i++) {
        g_rowptr[i] = base;
        g_cursor[i] = base;
        base += g_deg[i];
    }
    if (t == 0) g_rowptr[NN] = ET;
}

__global__ void scatter_kernel(const int* __restrict__ esrc, const int* __restrict__ edst)
{
    int idx = blockIdx.x * blockDim.x + threadIdx.x;
    if (idx >= ET) return;
    int s, d;
    if (idx < EE) { s = esrc[idx]; d = edst[idx]; }
    else          { s = d = idx - EE; }
    int pos = atomicAdd(&g_cursor[d], 1);
    g_csrsrc[pos] = s;
}

// ---------------- helpers ----------------
__device__ __forceinline__ uint32_t f2tf(float f) {
    uint32_t r;
    asm("cvt.rna.tf32.f32 %0, %1;" : "=r"(r) : "f"(f));
    return r;
}
__device__ __forceinline__ void cpa16(uint32_t d, const void* s, int sz) {
    asm volatile("cp.async.cg.shared.global [%0], [%1], 16, %2;"
                 :: "r"(d), "l"(s), "r"(sz));
}
__device__ __forceinline__ void cpa16u(uint32_t d, const void* s) {
    asm volatile("cp.async.cg.shared.global [%0], [%1], 16;"
                 :: "r"(d), "l"(s));
}

// ---------------- TF32 GEMM, cp.async double-buffered, fused concat+bias ----------------
// C[M, 2*Nh] = A[M,K] @ [Wl | Wr] + [bl | br]
__global__ __launch_bounds__(256, 2) void gemm_tf32_fused(
    const float* __restrict__ A, const float* __restrict__ Wl,
    const float* __restrict__ Wr, const float* __restrict__ bl,
    const float* __restrict__ br, float* __restrict__ C,
    int M, int K, int Nh)
{
    const int N = 2 * Nh;
    __shared__ uint32_t As[2][16][136];
    __shared__ float    Bs[2][16][136];
    int tid = threadIdx.x, lane = tid & 31, warp = tid >> 5;
    int wm = warp & 3, wn = warp >> 2;
    int rowBase = blockIdx.y * 128, colBase = blockIdx.x * 128;
    int grp = lane >> 2, tig = lane & 3;

    float acc[2][8][4];
    #pragma unroll
    for (int mt = 0; mt < 2; mt++)
        #pragma unroll
        for (int nt = 0; nt < 8; nt++)
            #pragma unroll
            for (int c = 0; c < 4; c++) acc[mt][nt][c] = 0.f;

    int nIter = K >> 4;

    float4 pa, pb;
    {
        int gr = rowBase + (tid >> 1);
        int kc = (tid & 1) * 8;
        pa = make_float4(0.f, 0.f, 0.f, 0.f); pb = pa;
        if (gr < M) {
            pa = *(const float4*)(A + (size_t)gr * K + kc);
            pb = *(const float4*)(A + (size_t)gr * K + kc + 4);
        }
    }
    {
        int rB = tid >> 4;
        int cB = (tid & 15) * 8;
        #pragma unroll
        for (int i = 0; i < 2; i++) {
            int gc = colBase + cB + i * 4;
            const float* src = Wl; int sz = 0;
            if (gc < Nh)      { src = Wl + (size_t)rB * Nh + gc;        sz = 16; }
            else if (gc < N)  { src = Wr + (size_t)rB * Nh + (gc - Nh); sz = 16; }
            cpa16((uint32_t)__cvta_generic_to_shared(&Bs[0][rB][cB + i * 4]), src, sz);
        }
    }
    {
        int r = tid >> 1, c4 = (tid & 1) * 8;
        As[0][c4 + 0][r] = f2tf(pa.x); As[0][c4 + 1][r] = f2tf(pa.y);
        As[0][c4 + 2][r] = f2tf(pa.z); As[0][c4 + 3][r] = f2tf(pa.w);
        As[0][c4 + 4][r] = f2tf(pb.x); As[0][c4 + 5][r] = f2tf(pb.y);
        As[0][c4 + 6][r] = f2tf(pb.z); As[0][c4 + 7][r] = f2tf(pb.w);
    }
    asm volatile("cp.async.commit_group;");

    int buf = 0;
    for (int it = 0; it < nIter; it++) {
        asm volatile("cp.async.wait_group 0;");
        __syncthreads();
        bool more = (it + 1 < nIter);
        if (more) {
            int k0 = (it + 1) << 4;
            int gr = rowBase + (tid >> 1);
            int kc = k0 + (tid & 1) * 8;
            pa = make_float4(0.f, 0.f, 0.f, 0.f); pb = pa;
            if (gr < M) {
                pa = *(const float4*)(A + (size_t)gr * K + kc);
                pb = *(const float4*)(A + (size_t)gr * K + kc + 4);
            }
            int rB = tid >> 4;
            int cB = (tid & 15) * 8;
            #pragma unroll
            for (int i = 0; i < 2; i++) {
                int gc = colBase + cB + i * 4;
                const float* src = Wl; int sz = 0;
                if (gc < Nh)      { src = Wl + (size_t)(k0 + rB) * Nh + gc;        sz = 16; }
                else if (gc < N)  { src = Wr + (size_t)(k0 + rB) * Nh + (gc - Nh); sz = 16; }
                cpa16((uint32_t)__cvta_generic_to_shared(&Bs[buf ^ 1][rB][cB + i * 4]), src, sz);
            }
            asm volatile("cp.async.commit_group;");
        }

        #pragma unroll
        for (int ks = 0; ks < 16; ks += 8) {
            uint32_t af[2][4], bf[8][2];
            #pragma unroll
            for (int mt = 0; mt < 2; mt++) {
                int m = wm * 32 + mt * 16;
                af[mt][0] = As[buf][ks + tig][m + grp];
                af[mt][1] = As[buf][ks + tig][m + grp + 8];
                af[mt][2] = As[buf][ks + tig + 4][m + grp];
                af[mt][3] = As[buf][ks + tig + 4][m + grp + 8];
            }
            #pragma unroll
            for (int nt = 0; nt < 8; nt++) {
                int nb = wn * 64 + nt * 8;
                bf[nt][0] = f2tf(Bs[buf][ks + tig][nb + grp]);
                bf[nt][1] = f2tf(Bs[buf][ks + tig + 4][nb + grp]);
            }
            #pragma unroll
            for (int mt = 0; mt < 2; mt++)
                #pragma unroll
                for (int nt = 0; nt < 8; nt++) {
                    asm volatile(
                        "mma.sync.aligned.m16n8k8.row.col.f32.tf32.tf32.f32 "
                        "{%0,%1,%2,%3}, {%4,%5,%6,%7}, {%8,%9}, {%0,%1,%2,%3};"
                        : "+f"(acc[mt][nt][0]), "+f"(acc[mt][nt][1]),
                          "+f"(acc[mt][nt][2]), "+f"(acc[mt][nt][3])
                        : "r"(af[mt][0]), "r"(af[mt][1]), "r"(af[mt][2]), "r"(af[mt][3]),
                          "r"(bf[nt][0]), "r"(bf[nt][1]));
                }
        }

        if (more) {
            int r = tid >> 1, c4 = (tid & 1) * 8;
            int b = buf ^ 1;
            As[b][c4 + 0][r] = f2tf(pa.x); As[b][c4 + 1][r] = f2tf(pa.y);
            As[b][c4 + 2][r] = f2tf(pa.z); As[b][c4 + 3][r] = f2tf(pa.w);
            As[b][c4 + 4][r] = f2tf(pb.x); As[b][c4 + 5][r] = f2tf(pb.y);
            As[b][c4 + 6][r] = f2tf(pb.z); As[b][c4 + 7][r] = f2tf(pb.w);
        }
        buf ^= 1;
    }

    #pragma unroll
    for (int mt = 0; mt < 2; mt++) {
        #pragma unroll
        for (int nt = 0; nt < 8; nt++) {
            int row0 = rowBase + wm * 32 + mt * 16 + grp;
            int col0 = colBase + wn * 64 + nt * 8 + tig * 2;
            if (col0 < N) {
                float b0 = (col0     < Nh) ? bl[col0]     : br[col0 - Nh];
                float b1 = (col0 + 1 < Nh) ? bl[col0 + 1] : br[col0 + 1 - Nh];
                if (row0 < M) {
                    float2 o = make_float2(acc[mt][nt][0] + b0, acc[mt][nt][1] + b1);
                    *(float2*)(C + (size_t)row0 * N + col0) = o;
                }
                if (row0 + 8 < M) {
                    float2 o = make_float2(acc[mt][nt][2] + b0, acc[mt][nt][3] + b1);
                    *(float2*)(C + (size_t)(row0 + 8) * N + col0) = o;
                }
            }
        }
    }
}

// ---------------- layer 1 agg: warp/node, cp.async ring (depth 4) ----------------
// Lane owns feats [lane*4, lane*4+4). Lane reads back only its own staged bytes.
__global__ __launch_bounds__(256) void agg1_kernel(
    const float* __restrict__ xc, const int* __restrict__ rowptr,
    const int* __restrict__ csrsrc, const float* __restrict__ att,
    const float* __restrict__ bias, float* __restrict__ hout)
{
    __shared__ float stage[8][D1][128];
    int wid  = threadIdx.x >> 5;
    int lane = threadIdx.x & 31;
    int node = (blockIdx.x * blockDim.x + threadIdx.x) >> 5;
    if (node >= NN) return;

    float4 vr = *(const float4*)(xc + (size_t)node * 256 + 128 + lane * 4);
    float4 va = *(const float4*)(att + lane * 4);

    int beg = rowptr[node];
    int deg = rowptr[node + 1] - beg;

    uint32_t sb = (uint32_t)__cvta_generic_to_shared(&stage[wid][0][0]) + lane * 16;

    #pragma unroll
    for (int j = 0; j < D1 - 1; j++) {
        if (j < deg) {
            int s = csrsrc[beg + j];
            cpa16u(sb + j * 512, xc + (size_t)s * 256 + lane * 4);
        }
        asm volatile("cp.async.commit_group;");
    }

    float4 acc = make_float4(0.f, 0.f, 0.f, 0.f);
    float ssum = 0.f;

    for (int i = 0; i < deg; i++) {
        asm volatile("cp.async.wait_group %0;" :: "n"(D1 - 2));
        float4 c = *(const float4*)&stage[wid][i & (D1 - 1)][lane * 4];

        int nb = i + D1 - 1;
        if (nb < deg) {
            int s = csrsrc[beg + nb];
            cpa16u(sb + (nb & (D1 - 1)) * 512, xc + (size_t)s * 256 + lane * 4);
        }
        asm volatile("cp.async.commit_group;");

        float g, p = 0.f;
        g = c.x + vr.x; g = g > 0.f ? g : SLOPE * g; p += g * va.x;
        g = c.y + vr.y; g = g > 0.f ? g : SLOPE * g; p += g * va.y;
        g = c.z + vr.z; g = g > 0.f ? g : SLOPE * g; p += g * va.z;
        g = c.w + vr.w; g = g > 0.f ? g : SLOPE * g; p += g * va.w;
        p += __shfl_xor_sync(FULLMASK, p, 1);
        p += __shfl_xor_sync(FULLMASK, p, 2);
        p += __shfl_xor_sync(FULLMASK, p, 4);
        float a = __expf(p);
        acc.x += a * c.x; acc.y += a * c.y; acc.z += a * c.z; acc.w += a * c.w;
        ssum += a;
    }

    float inv = 1.f / (ssum + 1e-16f);
    float4 bv = *(const float4*)(bias + lane * 4);
    float4 o;
    o.x = acc.x * inv + bv.x;
    o.y = acc.y * inv + bv.y;
    o.z = acc.z * inv + bv.z;
    o.w = acc.w * inv + bv.w;
    o.x = o.x > 0.f ? o.x : (__expf(o.x) - 1.f);
    o.y = o.y > 0.f ? o.y : (__expf(o.y) - 1.f);
    o.z = o.z > 0.f ? o.z : (__expf(o.z) - 1.f);
    o.w = o.w > 0.f ? o.w : (__expf(o.w) - 1.f);
    *(float4*)(hout + (size_t)node * F1 + lane * 4) = o;
}

// ---------------- layer 2 agg: warp/node, cp.async ring (depth 4) ----------------
// Lane owns feats [lane*5, lane*5+5); staging is cross-lane -> __syncwarp after wait.
__global__ __launch_bounds__(256) void agg2_kernel(
    const float* __restrict__ xc, const int* __restrict__ rowptr,
    const int* __restrict__ csrsrc, const float* __restrict__ att,
    const float* __restrict__ bias, float* __restrict__ out)
{
    __shared__ float stage[8][D2][160];
    int wid  = threadIdx.x >> 5;
    int lane = threadIdx.x & 31;
    int node = (blockIdx.x * blockDim.x + threadIdx.x) >> 5;
    if (node >= NN) return;
    int base = lane * 5;   // head = lane>>3

    float vr[5], va[5];
    const float* vp = xc + (size_t)node * 320 + 160 + base;
    #pragma unroll
    for (int j = 0; j < 5; j++) {
        vr[j] = vp[j];
        va[j] = att[base + j];
    }

    int beg = rowptr[node];
    int deg = rowptr[node + 1] - beg;

    uint32_t sb0 = (uint32_t)__cvta_generic_to_shared(&stage[wid][0][0]);

    #pragma unroll
    for (int j = 0; j < D2 - 1; j++) {
        if (j < deg) {
            int s = csrsrc[beg + j];
            const float* src = xc + (size_t)s * 320;
            cpa16u(sb0 + j * 640 + lane * 16, src + lane * 4);
            if (lane < 8)
                cpa16u(sb0 + j * 640 + 512 + lane * 16, src + 128 + lane * 4);
        }
        asm volatile("cp.async.commit_group;");
    }

    float acc[5] = {0.f, 0.f, 0.f, 0.f, 0.f};
    float ssum = 0.f;

    for (int i = 0; i < deg; i++) {
        asm volatile("cp.async.wait_group %0;" :: "n"(D2 - 2));
        __syncwarp();
        const float* sp = &stage[wid][i & (D2 - 1)][0];
        float c[5];
        #pragma unroll
        for (int j = 0; j < 5; j++) c[j] = sp[base + j];

        int nb = i + D2 - 1;
        if (nb < deg) {
            int s = csrsrc[beg + nb];
            const float* src = xc + (size_t)s * 320;
            int slot = nb & (D2 - 1);
            cpa16u(sb0 + slot * 640 + lane * 16, src + lane * 4);
            if (lane < 8)
                cpa16u(sb0 + slot * 640 + 512 + lane * 16, src + 128 + lane * 4);
        }
        asm volatile("cp.async.commit_group;");

        float p = 0.f;
        #pragma unroll
        for (int j = 0; j < 5; j++) {
            float g = c[j] + vr[j];
            g = g > 0.f ? g : SLOPE * g;
            p += g * va[j];
        }
        p += __shfl_xor_sync(FULLMASK, p, 1);
        p += __shfl_xor_sync(FULLMASK, p, 2);
        p += __shfl_xor_sync(FULLMASK, p, 4);
        float a = __expf(p);
        #pragma unroll
        for (int j = 0; j < 5; j++) acc[j] += a * c[j];
        ssum += a;
    }

    float inv = 1.f / (ssum + 1e-16f);
    #pragma unroll
    for (int j = 0; j < 5; j++) {
        float v = acc[j] * inv;
        v += __shfl_xor_sync(FULLMASK, v, 8);
        v += __shfl_xor_sync(FULLMASK, v, 16);
        acc[j] = 0.25f * v;
    }
    if (lane < 8) {
        #pragma unroll
        for (int j = 0; j < 5; j++)
            out[(size_t)node * OUT_DIM + base + j] = acc[j] + bias[base + j];
    }
}

// ---------------- host ----------------
struct Ptrs {
    float *xc1, *xc2, *h;
    int *deg, *rowptr, *csrsrc;
};
static Ptrs P;
static cudaStream_t g_s2;
static cudaEvent_t g_ev1, g_ev2;
static bool g_init = false;

extern "C" void kernel_launch(void* const* d_in, const int* in_sizes, int n_in,
                              void* d_out, int out_size)
{
    if (!g_init) {
        cudaGetSymbolAddress((void**)&P.xc1,    g_xc1);
        cudaGetSymbolAddress((void**)&P.xc2,    g_xc2);
        cudaGetSymbolAddress((void**)&P.h,      g_h);
        cudaGetSymbolAddress((void**)&P.deg,    g_deg);
        cudaGetSymbolAddress((void**)&P.rowptr, g_rowptr);
        cudaGetSymbolAddress((void**)&P.csrsrc, g_csrsrc);
        cudaStreamCreateWithFlags(&g_s2, cudaStreamNonBlocking);
        cudaEventCreateWithFlags(&g_ev1, cudaEventDisableTiming);
        cudaEventCreateWithFlags(&g_ev2, cudaEventDisableTiming);
        g_init = true;
    }

    const float* x     = (const float*)d_in[0];
    const int*   ei    = (const int*)  d_in[1];
    const float* Wl1   = (const float*)d_in[2];
    const float* bl1   = (const float*)d_in[3];
    const float* Wr1   = (const float*)d_in[4];
    const float* br1   = (const float*)d_in[5];
    const float* att1  = (const float*)d_in[6];
    const float* bias1 = (const float*)d_in[7];
    const float* Wl2   = (const float*)d_in[8];
    const float* bl2   = (const float*)d_in[9];
    const float* Wr2   = (const float*)d_in[10];
    const float* br2   = (const float*)d_in[11];
    const float* att2  = (const float*)d_in[12];
    const float* bias2 = (const float*)d_in[13];
    float* out = (float*)d_out;

    const int* esrc = ei;
    const int* edst = ei + EE;

    // fork: CSR build on side stream, concurrent with GEMM1
    cudaEventRecord(g_ev1, 0);
    cudaStreamWaitEvent(g_s2, g_ev1, 0);
    cudaMemsetAsync(P.deg, 0, NN * sizeof(int), g_s2);
    count_kernel<<<(ET + 255) / 256, 256, 0, g_s2>>>(edst);
    scan_kernel<<<1, 1024, 0, g_s2>>>();
    scatter_kernel<<<(ET + 255) / 256, 256, 0, g_s2>>>(esrc, edst);
    cudaEventRecord(g_ev2, g_s2);

    // ----- layer 1 GEMM (main stream) -----
    {
        dim3 grid(2, (NN + 127) / 128);
        gemm_tf32_fused<<<grid, 256>>>(x, Wl1, Wr1, bl1, br1, P.xc1, NN, IN_DIM, F1);
    }
    cudaStreamWaitEvent(0, g_ev2, 0);
    agg1_kernel<<<(NN * 32 + 255) / 256, 256>>>(P.xc1, P.rowptr, P.csrsrc, att1, bias1, P.h);

    // ----- layer 2 -----
    {
        dim3 grid(3, (NN + 127) / 128);
        gemm_tf32_fused<<<grid, 256>>>(P.h, Wl2, Wr2, bl2, br2, P.xc2, NN, F1, F2);
    }
    agg2_kernel<<<(NN * 32 + 255) / 256, 256>>>(P.xc2, P.rowptr, P.csrsrc, att2, bias2, out);
}